// round 6
// baseline (speedup 1.0000x reference)
#include <cuda_runtime.h>
#include <cuda_bf16.h>
#include <cstdint>

// Problem constants (match reference_code)
#define NPTS   1000000
#define NCH    32
#define SDIM   64
#define NKEYS  (SDIM*SDIM*SDIM*SDIM)      // 16,777,216 possible keys (2^24)
#define NWORDS (NKEYS/32)                 // 524,288 bitmap words
#define SCAN_BLOCKS 512                   // 512 blocks * 256 thr * 4 words = 524,288
#define WORDS_PER_THREAD 4

// ---- device scratch (static; no allocation allowed) ----
__device__ unsigned int g_bits[NWORDS];      // presence bitmap (2MB)
__device__ unsigned int g_dup[NWORDS];       // "key has >1 point" bitmap (2MB)
__device__ unsigned int g_prefix[NWORDS];    // exclusive popcount prefix per word (2MB)
__device__ int          g_keys[NPTS];        // cached key per point (4MB)
__device__ unsigned int g_blockSums[SCAN_BLOCKS];
__device__ unsigned int g_total;             // number of unique keys U

// ------------------------------------------------------------------
// K1: zero both bitmaps (must reset every launch for graph replay)
// ------------------------------------------------------------------
__global__ void k_zero_bits() {
    int t = blockIdx.x * blockDim.x + threadIdx.x;   // NWORDS/4 threads
    uint4 z = make_uint4(0u, 0u, 0u, 0u);
    reinterpret_cast<uint4*>(g_bits)[t] = z;
    reinterpret_cast<uint4*>(g_dup)[t]  = z;
}

// ------------------------------------------------------------------
// K2: compute keys, mark presence, detect duplicates
// ------------------------------------------------------------------
__global__ void k_mark(const int4* __restrict__ coords) {
    int i = blockIdx.x * blockDim.x + threadIdx.x;
    if (i >= NPTS) return;
    int4 c = coords[i];
    int key = ((c.x * SDIM + c.y) * SDIM + c.z) * SDIM + c.w;
    g_keys[i] = key;
    unsigned bit = 1u << (key & 31);
    unsigned old = atomicOr(&g_bits[key >> 5], bit);
    if (old & bit) atomicOr(&g_dup[key >> 5], bit);
}

// ------------------------------------------------------------------
// K3: per-block popcount sums (scan pass A)
// ------------------------------------------------------------------
__global__ void k_scan_reduce() {
    int blk = blockIdx.x, tid = threadIdx.x;
    int wbase = blk * (256 * WORDS_PER_THREAD) + tid * WORDS_PER_THREAD;
    uint4 w = *reinterpret_cast<const uint4*>(&g_bits[wbase]);
    unsigned tsum = __popc(w.x) + __popc(w.y) + __popc(w.z) + __popc(w.w);
    // warp reduce
    #pragma unroll
    for (int d = 16; d > 0; d >>= 1)
        tsum += __shfl_down_sync(0xffffffffu, tsum, d);
    __shared__ unsigned ws[8];
    int lane = tid & 31, wid = tid >> 5;
    if (lane == 0) ws[wid] = tsum;
    __syncthreads();
    if (tid < 8) {
        unsigned x = ws[tid];
        #pragma unroll
        for (int d = 4; d > 0; d >>= 1)
            x += __shfl_down_sync(0xffu, x, d);
        if (tid == 0) g_blockSums[blk] = x;
    }
}

// ------------------------------------------------------------------
// K4: exclusive scan of 512 block sums (single block), record U
// ------------------------------------------------------------------
__global__ void k_scan_mid() {
    int tid = threadIdx.x;                    // 512 threads
    int lane = tid & 31, wid = tid >> 5;      // 16 warps
    unsigned v = g_blockSums[tid];
    unsigned inc = v;
    #pragma unroll
    for (int d = 1; d < 32; d <<= 1) {
        unsigned n = __shfl_up_sync(0xffffffffu, inc, d);
        if (lane >= d) inc += n;
    }
    __shared__ unsigned ws[16];
    if (lane == 31) ws[wid] = inc;
    __syncthreads();
    if (tid < 16) {
        unsigned x = ws[tid];
        unsigned s = x;
        #pragma unroll
        for (int d = 1; d < 16; d <<= 1) {
            unsigned n = __shfl_up_sync(0xffffu, s, d);
            if (tid >= d) s += n;
        }
        ws[tid] = s - x;                      // exclusive warp offsets
    }
    __syncthreads();
    unsigned total_inc = ws[wid] + inc;       // block-wide inclusive
    g_blockSums[tid] = total_inc - v;         // exclusive
    if (tid == 511) g_total = total_inc;      // U = total unique keys
}

// ------------------------------------------------------------------
// K5: per-word exclusive prefix (scan pass C)
// ------------------------------------------------------------------
__global__ void k_scan_write() {
    int blk = blockIdx.x, tid = threadIdx.x;
    int lane = tid & 31, wid = tid >> 5;
    int wbase = blk * (256 * WORDS_PER_THREAD) + tid * WORDS_PER_THREAD;
    uint4 w = *reinterpret_cast<const uint4*>(&g_bits[wbase]);
    unsigned c0 = __popc(w.x), c1 = __popc(w.y), c2 = __popc(w.z), c3 = __popc(w.w);
    unsigned tsum = c0 + c1 + c2 + c3;
    unsigned inc = tsum;
    #pragma unroll
    for (int d = 1; d < 32; d <<= 1) {
        unsigned n = __shfl_up_sync(0xffffffffu, inc, d);
        if (lane >= d) inc += n;
    }
    __shared__ unsigned ws[8];
    __shared__ unsigned woff[8];
    if (lane == 31) ws[wid] = inc;
    __syncthreads();
    if (tid < 8) {
        unsigned x = ws[tid];
        unsigned s = x;
        #pragma unroll
        for (int d = 1; d < 8; d <<= 1) {
            unsigned n = __shfl_up_sync(0xffu, s, d);
            if (tid >= d) s += n;
        }
        woff[tid] = s - x;
    }
    __syncthreads();
    unsigned excl = g_blockSums[blk] + woff[wid] + (inc - tsum);
    uint4 p;
    p.x = excl;
    p.y = excl + c0;
    p.z = excl + c0 + c1;
    p.w = excl + c0 + c1 + c2;
    *reinterpret_cast<uint4*>(&g_prefix[wbase]) = p;
}

// ------------------------------------------------------------------
// K6: zero dup-key rows and tail rows [U, N)   (8 lanes per point)
// ------------------------------------------------------------------
__global__ void k_zero_rows(float4* __restrict__ out4) {
    int t = blockIdx.x * blockDim.x + threadIdx.x;
    int i = t >> 3;
    int sub = t & 7;
    if (i >= NPTS) return;
    float4 z = make_float4(0.f, 0.f, 0.f, 0.f);
    unsigned U = g_total;
    if ((unsigned)i >= U)
        out4[(size_t)i * 8 + sub] = z;
    int key = g_keys[i];
    unsigned word_idx = (unsigned)key >> 5;
    unsigned bit = (unsigned)key & 31;
    if ((g_dup[word_idx] >> bit) & 1u) {
        unsigned rank = g_prefix[word_idx] +
                        __popc(g_bits[word_idx] & ((1u << bit) - 1u));
        out4[(size_t)rank * 8 + sub] = z;
    }
}

// ------------------------------------------------------------------
// K7: scatter features. Sole-owner keys: plain float4 stores (full
// cacheline per row, no RMW). Dup keys: atomicAdd into zeroed rows.
// ------------------------------------------------------------------
__global__ void k_scatter(const float4* __restrict__ feats,
                          float* __restrict__ out) {
    int t = blockIdx.x * blockDim.x + threadIdx.x;
    int i = t >> 3;
    int sub = t & 7;
    if (i >= NPTS) return;
    int key = g_keys[i];
    unsigned word_idx = (unsigned)key >> 5;
    unsigned bit = (unsigned)key & 31;
    unsigned bw = g_bits[word_idx];
    unsigned rank = g_prefix[word_idx] + __popc(bw & ((1u << bit) - 1u));
    float4 v = feats[(size_t)i * 8 + sub];
    float* dst = out + (size_t)rank * NCH + sub * 4;
    bool dup = (g_dup[word_idx] >> bit) & 1u;
    if (!dup) {
        *reinterpret_cast<float4*>(dst) = v;
    } else {
        atomicAdd(dst + 0, v.x);
        atomicAdd(dst + 1, v.y);
        atomicAdd(dst + 2, v.z);
        atomicAdd(dst + 3, v.w);
    }
}

// ------------------------------------------------------------------
extern "C" void kernel_launch(void* const* d_in, const int* in_sizes, int n_in,
                              void* d_out, int out_size) {
    const int4*   coords = (const int4*)d_in[0];     // [N,4] int32
    const float4* feats  = (const float4*)d_in[1];   // [N,32] f32 as [N,8] float4
    float*        out    = (float*)d_out;            // [N,32] f32

    (void)in_sizes; (void)n_in; (void)out_size;

    const int TB = 256;

    // K1: reset bitmaps (NWORDS/4 uint4 stores, x2 arrays)
    k_zero_bits<<<NWORDS / 4 / TB, TB>>>();
    // K2: keys + presence + dup detection
    k_mark<<<(NPTS + TB - 1) / TB, TB>>>(coords);
    // K3-K5: popcount prefix scan over the bitmap
    k_scan_reduce<<<SCAN_BLOCKS, TB>>>();
    k_scan_mid<<<1, 512>>>();
    k_scan_write<<<SCAN_BLOCKS, TB>>>();
    // K6: zero rows that need it (dup-key rows + tail rows >= U)
    k_zero_rows<<<(NPTS * 8) / TB, TB>>>((float4*)d_out);
    // K7: scatter
    k_scatter<<<(NPTS * 8) / TB, TB>>>(feats, out);
}

// round 7
// speedup vs baseline: 1.3074x; 1.3074x over previous
#include <cuda_runtime.h>
#include <cuda_bf16.h>
#include <cstdint>

// Problem constants (match reference_code)
#define NPTS   1000000
#define NCH    32
#define SDIM   64
#define NKEYS  (SDIM*SDIM*SDIM*SDIM)      // 16,777,216 possible keys (2^24)
#define NWORDS (NKEYS/32)                 // 524,288 bitmap words

// Fused scan config: 128 blocks * 256 threads * 16 words = 524,288
#define SCAN_NBLK 128
#define SCAN_TPB  256
#define WPT       16

// ---- device scratch (static; no allocation allowed) ----
__device__ unsigned int g_bits[NWORDS];      // presence bitmap (2MB)
__device__ unsigned int g_dup[NWORDS];       // "key has >1 point" bitmap (2MB)
__device__ unsigned int g_prefix[NWORDS];    // exclusive popcount prefix per word (2MB)
__device__ int          g_keys[NPTS];        // cached key per point (4MB)
__device__ unsigned int g_desc[SCAN_NBLK];   // decoupled-lookback descriptors
__device__ unsigned int g_total;             // number of unique keys U

// ------------------------------------------------------------------
// K1: zero bitmaps + lookback descriptors (reset every graph replay)
// ------------------------------------------------------------------
__global__ void k_zero_bits() {
    int t = blockIdx.x * blockDim.x + threadIdx.x;   // NWORDS/4 threads
    uint4 z = make_uint4(0u, 0u, 0u, 0u);
    reinterpret_cast<uint4*>(g_bits)[t] = z;
    reinterpret_cast<uint4*>(g_dup)[t]  = z;
    if (t < SCAN_NBLK / 4)
        reinterpret_cast<uint4*>(g_desc)[t] = z;
}

// ------------------------------------------------------------------
// K2: compute keys, mark presence, detect duplicates
// ------------------------------------------------------------------
__global__ void k_mark(const int4* __restrict__ coords) {
    int i = blockIdx.x * blockDim.x + threadIdx.x;
    if (i >= NPTS) return;
    int4 c = coords[i];
    int key = ((c.x * SDIM + c.y) * SDIM + c.z) * SDIM + c.w;
    g_keys[i] = key;
    unsigned bit = 1u << (key & 31);
    unsigned old = atomicOr(&g_bits[key >> 5], bit);
    if (old & bit) atomicOr(&g_dup[key >> 5], bit);
}

// ------------------------------------------------------------------
// K3: fused single-pass scan (decoupled lookback) + prefix write +
//     dup-row zeroing + U capture.
// Status word: bits[30:32) = {0 invalid, 1 aggregate, 2 prefix},
//              bits[0:30)  = value (U <= 1M fits easily).
// 128 blocks <= 148 SMs -> all resident in wave 1, lookback is safe.
// ------------------------------------------------------------------
__global__ void __launch_bounds__(SCAN_TPB, 1)
k_scan_fused(float4* __restrict__ out4) {
    const unsigned FULL = 0xffffffffu;
    int bid = blockIdx.x, tid = threadIdx.x;
    int lane = tid & 31, wid = tid >> 5;
    int wbase = bid * (SCAN_TPB * WPT) + tid * WPT;

    // ---- load 16 bitmap words + 16 dup words (vectorized) ----
    unsigned w[WPT], dw[WPT], c[WPT];
    #pragma unroll
    for (int j = 0; j < 4; j++) {
        uint4 v = *reinterpret_cast<const uint4*>(&g_bits[wbase + j * 4]);
        w[j*4+0] = v.x; w[j*4+1] = v.y; w[j*4+2] = v.z; w[j*4+3] = v.w;
        uint4 d = *reinterpret_cast<const uint4*>(&g_dup[wbase + j * 4]);
        dw[j*4+0] = d.x; dw[j*4+1] = d.y; dw[j*4+2] = d.z; dw[j*4+3] = d.w;
    }
    unsigned tsum = 0;
    #pragma unroll
    for (int j = 0; j < WPT; j++) { c[j] = __popc(w[j]); tsum += c[j]; }

    // ---- warp inclusive scan of thread sums ----
    unsigned inc = tsum;
    #pragma unroll
    for (int d = 1; d < 32; d <<= 1) {
        unsigned n = __shfl_up_sync(FULL, inc, d);
        if (lane >= d) inc += n;
    }

    __shared__ unsigned ws[8], woff[8];
    __shared__ unsigned sh_agg, sh_excl;
    if (lane == 31) ws[wid] = inc;
    __syncthreads();
    if (tid < 8) {
        unsigned x = ws[tid], s = x;
        #pragma unroll
        for (int d = 1; d < 8; d <<= 1) {
            unsigned n = __shfl_up_sync(0xffu, s, d);
            if (tid >= d) s += n;
        }
        woff[tid] = s - x;
        if (tid == 7) sh_agg = s;            // block aggregate
    }
    __syncthreads();
    unsigned agg = sh_agg;

    // ---- publish + decoupled lookback (warp 0) ----
    if (wid == 0) {
        if (bid == 0) {
            if (lane == 0) {
                atomicExch(&g_desc[0], (2u << 30) | agg);
                sh_excl = 0;
            }
        } else {
            if (lane == 0) atomicExch(&g_desc[bid], (1u << 30) | agg);
            unsigned running = 0;
            int base = bid - 1;
            while (true) {
                int idx = base - lane;
                unsigned d = (idx >= 0) ? atomicAdd(&g_desc[idx], 0u)
                                        : (2u << 30);           // virtual prefix 0
                unsigned st = d >> 30;
                if (__ballot_sync(FULL, st == 0)) continue;     // spin until window ready
                unsigned pm  = __ballot_sync(FULL, st == 2);
                unsigned val = d & 0x3fffffffu;
                if (pm) {
                    int p = __ffs(pm) - 1;                      // closest prefix block
                    if (lane > p) val = 0;
                }
                #pragma unroll
                for (int dd = 16; dd > 0; dd >>= 1)
                    val += __shfl_down_sync(FULL, val, dd);
                running += __shfl_sync(FULL, val, 0);
                if (pm) break;
                base -= 32;
            }
            if (lane == 0) {
                atomicExch(&g_desc[bid], (2u << 30) | (running + agg));
                sh_excl = running;
                if (bid == SCAN_NBLK - 1) g_total = running + agg;
            }
        }
    }
    __syncthreads();

    // ---- per-word exclusive prefixes ----
    unsigned run = sh_excl + woff[wid] + (inc - tsum);
    unsigned p[WPT];
    #pragma unroll
    for (int j = 0; j < WPT; j++) { p[j] = run; run += c[j]; }
    #pragma unroll
    for (int j = 0; j < 4; j++) {
        uint4 v = make_uint4(p[j*4+0], p[j*4+1], p[j*4+2], p[j*4+3]);
        *reinterpret_cast<uint4*>(&g_prefix[wbase + j * 4]) = v;
    }

    // ---- zero the rows owned by duplicate keys (sparse, ~30K rows) ----
    float4 z = make_float4(0.f, 0.f, 0.f, 0.f);
    #pragma unroll
    for (int j = 0; j < WPT; j++) {
        unsigned d = dw[j];
        while (d) {
            int b = __ffs(d) - 1;
            d &= d - 1;
            unsigned rank = p[j] + __popc(w[j] & ((1u << b) - 1u));
            float4* row = out4 + (size_t)rank * 8;
            #pragma unroll
            for (int q = 0; q < 8; q++) row[q] = z;
        }
    }
}

// ------------------------------------------------------------------
// K4: scatter features + zero tail rows [U, N).
// Sole-owner keys (~94%): plain float4 stores (full cacheline, no RMW).
// Dup keys: atomicAdd into rows zeroed by K3.
// ------------------------------------------------------------------
__global__ void k_scatter(const float4* __restrict__ feats,
                          float* __restrict__ out) {
    int t = blockIdx.x * blockDim.x + threadIdx.x;
    int i = t >> 3;
    int sub = t & 7;                       // NPTS*8 threads exactly

    unsigned U = g_total;
    if ((unsigned)i >= U) {                // tail row zeroing
        reinterpret_cast<float4*>(out)[(size_t)i * 8 + sub] =
            make_float4(0.f, 0.f, 0.f, 0.f);
    }

    int key = g_keys[i];
    unsigned word_idx = (unsigned)key >> 5;
    unsigned bit = (unsigned)key & 31;
    unsigned bw = g_bits[word_idx];
    unsigned rank = g_prefix[word_idx] + __popc(bw & ((1u << bit) - 1u));
    float4 v = feats[(size_t)i * 8 + sub];
    float* dst = out + (size_t)rank * NCH + sub * 4;
    bool dup = (g_dup[word_idx] >> bit) & 1u;
    if (!dup) {
        *reinterpret_cast<float4*>(dst) = v;
    } else {
        atomicAdd(dst + 0, v.x);
        atomicAdd(dst + 1, v.y);
        atomicAdd(dst + 2, v.z);
        atomicAdd(dst + 3, v.w);
    }
}

// ------------------------------------------------------------------
extern "C" void kernel_launch(void* const* d_in, const int* in_sizes, int n_in,
                              void* d_out, int out_size) {
    const int4*   coords = (const int4*)d_in[0];     // [N,4] int32
    const float4* feats  = (const float4*)d_in[1];   // [N,32] f32 as [N,8] float4
    float*        out    = (float*)d_out;            // [N,32] f32

    (void)in_sizes; (void)n_in; (void)out_size;

    const int TB = 256;

    // K1: reset bitmaps + lookback descriptors
    k_zero_bits<<<NWORDS / 4 / TB, TB>>>();
    // K2: keys + presence + dup detection
    k_mark<<<(NPTS + TB - 1) / TB, TB>>>(coords);
    // K3: fused single-pass scan + prefix + dup-row zero + U
    k_scan_fused<<<SCAN_NBLK, SCAN_TPB>>>((float4*)d_out);
    // K4: scatter + tail zero
    k_scatter<<<(NPTS * 8) / TB, TB>>>(feats, out);
}

// round 8
// speedup vs baseline: 1.4197x; 1.0859x over previous
#include <cuda_runtime.h>
#include <cuda_bf16.h>
#include <cstdint>

// Problem constants (match reference_code)
#define NPTS   1000000
#define NCH    32
#define SDIM   64
#define NKEYS  (SDIM*SDIM*SDIM*SDIM)      // 16,777,216 possible keys (2^24)
#define NWORDS (NKEYS/32)                 // 524,288 bitmap words

// Fused scan config: 128 blocks * 256 threads * 16 words = 524,288
#define SCAN_NBLK 128
#define SCAN_TPB  256
#define WPT       16

// ---- device scratch (static; no allocation allowed) ----
__device__ unsigned int g_bits[NWORDS];      // presence bitmap (2MB)
__device__ unsigned int g_dup[NWORDS];       // "key has >1 point" bitmap (2MB)
__device__ unsigned int g_prefix[NWORDS];    // exclusive popcount prefix per word (2MB)
__device__ int          g_keys[NPTS];        // cached key per point (4MB)
__device__ unsigned int g_desc[SCAN_NBLK];   // decoupled-lookback descriptors
__device__ unsigned int g_total;             // number of unique keys U

// ------------------------------------------------------------------
// K1: zero bitmaps + lookback descriptors (reset every graph replay)
// ------------------------------------------------------------------
__global__ void k_zero_bits() {
    int t = blockIdx.x * blockDim.x + threadIdx.x;   // NWORDS/4 threads
    uint4 z = make_uint4(0u, 0u, 0u, 0u);
    reinterpret_cast<uint4*>(g_bits)[t] = z;
    reinterpret_cast<uint4*>(g_dup)[t]  = z;
    if (t < SCAN_NBLK / 4)
        reinterpret_cast<uint4*>(g_desc)[t] = z;
}

// ------------------------------------------------------------------
// K2: compute keys, mark presence, detect duplicates (2 pts/thread)
// ------------------------------------------------------------------
__global__ void k_mark(const int4* __restrict__ coords) {
    const int HALF = NPTS / 2;
    int i = blockIdx.x * blockDim.x + threadIdx.x;
    if (i >= HALF) return;
    int4 c0 = coords[i];
    int4 c1 = coords[i + HALF];
    int k0 = ((c0.x * SDIM + c0.y) * SDIM + c0.z) * SDIM + c0.w;
    int k1 = ((c1.x * SDIM + c1.y) * SDIM + c1.z) * SDIM + c1.w;
    g_keys[i]        = k0;
    g_keys[i + HALF] = k1;
    unsigned b0 = 1u << (k0 & 31);
    unsigned b1 = 1u << (k1 & 31);
    unsigned o0 = atomicOr(&g_bits[k0 >> 5], b0);
    unsigned o1 = atomicOr(&g_bits[k1 >> 5], b1);
    if (o0 & b0) atomicOr(&g_dup[k0 >> 5], b0);
    if (o1 & b1) atomicOr(&g_dup[k1 >> 5], b1);
}

// ------------------------------------------------------------------
// K3: fused single-pass scan (decoupled lookback) + prefix write +
//     dup-row zeroing + U capture.
// ------------------------------------------------------------------
__global__ void __launch_bounds__(SCAN_TPB, 1)
k_scan_fused(float4* __restrict__ out4) {
    const unsigned FULL = 0xffffffffu;
    int bid = blockIdx.x, tid = threadIdx.x;
    int lane = tid & 31, wid = tid >> 5;
    int wbase = bid * (SCAN_TPB * WPT) + tid * WPT;

    unsigned w[WPT], dw[WPT], c[WPT];
    #pragma unroll
    for (int j = 0; j < 4; j++) {
        uint4 v = *reinterpret_cast<const uint4*>(&g_bits[wbase + j * 4]);
        w[j*4+0] = v.x; w[j*4+1] = v.y; w[j*4+2] = v.z; w[j*4+3] = v.w;
        uint4 d = *reinterpret_cast<const uint4*>(&g_dup[wbase + j * 4]);
        dw[j*4+0] = d.x; dw[j*4+1] = d.y; dw[j*4+2] = d.z; dw[j*4+3] = d.w;
    }
    unsigned tsum = 0;
    #pragma unroll
    for (int j = 0; j < WPT; j++) { c[j] = __popc(w[j]); tsum += c[j]; }

    unsigned inc = tsum;
    #pragma unroll
    for (int d = 1; d < 32; d <<= 1) {
        unsigned n = __shfl_up_sync(FULL, inc, d);
        if (lane >= d) inc += n;
    }

    __shared__ unsigned ws[8], woff[8];
    __shared__ unsigned sh_agg, sh_excl;
    if (lane == 31) ws[wid] = inc;
    __syncthreads();
    if (tid < 8) {
        unsigned x = ws[tid], s = x;
        #pragma unroll
        for (int d = 1; d < 8; d <<= 1) {
            unsigned n = __shfl_up_sync(0xffu, s, d);
            if (tid >= d) s += n;
        }
        woff[tid] = s - x;
        if (tid == 7) sh_agg = s;
    }
    __syncthreads();
    unsigned agg = sh_agg;

    if (wid == 0) {
        if (bid == 0) {
            if (lane == 0) {
                atomicExch(&g_desc[0], (2u << 30) | agg);
                sh_excl = 0;
            }
        } else {
            if (lane == 0) atomicExch(&g_desc[bid], (1u << 30) | agg);
            unsigned running = 0;
            int base = bid - 1;
            while (true) {
                int idx = base - lane;
                unsigned d = (idx >= 0) ? atomicAdd(&g_desc[idx], 0u)
                                        : (2u << 30);
                unsigned st = d >> 30;
                if (__ballot_sync(FULL, st == 0)) continue;
                unsigned pm  = __ballot_sync(FULL, st == 2);
                unsigned val = d & 0x3fffffffu;
                if (pm) {
                    int p = __ffs(pm) - 1;
                    if (lane > p) val = 0;
                }
                #pragma unroll
                for (int dd = 16; dd > 0; dd >>= 1)
                    val += __shfl_down_sync(FULL, val, dd);
                running += __shfl_sync(FULL, val, 0);
                if (pm) break;
                base -= 32;
            }
            if (lane == 0) {
                atomicExch(&g_desc[bid], (2u << 30) | (running + agg));
                sh_excl = running;
                if (bid == SCAN_NBLK - 1) g_total = running + agg;
            }
        }
    }
    __syncthreads();

    unsigned run = sh_excl + woff[wid] + (inc - tsum);
    unsigned p[WPT];
    #pragma unroll
    for (int j = 0; j < WPT; j++) { p[j] = run; run += c[j]; }
    #pragma unroll
    for (int j = 0; j < 4; j++) {
        uint4 v = make_uint4(p[j*4+0], p[j*4+1], p[j*4+2], p[j*4+3]);
        *reinterpret_cast<uint4*>(&g_prefix[wbase + j * 4]) = v;
    }

    // zero the rows owned by duplicate keys (sparse, ~30K rows)
    float4 z = make_float4(0.f, 0.f, 0.f, 0.f);
    #pragma unroll
    for (int j = 0; j < WPT; j++) {
        unsigned d = dw[j];
        while (d) {
            int b = __ffs(d) - 1;
            d &= d - 1;
            unsigned rank = p[j] + __popc(w[j] & ((1u << b) - 1u));
            float4* row = out4 + (size_t)rank * 8;
            #pragma unroll
            for (int q = 0; q < 8; q++) row[q] = z;
        }
    }
}

// ------------------------------------------------------------------
// K4: scatter features + zero tail rows [U, N).
// 4 threads per row, 2 float4 each. Metadata computed once per row
// by a leader lane and broadcast via shuffle. Streaming cache hints
// keep the 6MB metadata arrays resident in L2.
// ------------------------------------------------------------------
__global__ void __launch_bounds__(256)
k_scatter(const float4* __restrict__ feats, float* __restrict__ out) {
    const unsigned FULL = 0xffffffffu;
    int t = blockIdx.x * blockDim.x + threadIdx.x;   // NPTS*4 threads exactly
    int i = t >> 2;                                  // point / row index
    int lane = threadIdx.x & 31;
    int s = lane & 3;                                // float4 slot 0..3 (and +4)

    unsigned U = g_total;

    // metadata: leader lane of each 4-lane group
    unsigned rd = 0;
    if (s == 0) {
        int key = g_keys[i];
        unsigned word_idx = (unsigned)key >> 5;
        unsigned bit = (unsigned)key & 31;
        unsigned bw   = g_bits[word_idx];
        unsigned rank = g_prefix[word_idx] + __popc(bw & ((1u << bit) - 1u));
        unsigned dup  = (g_dup[word_idx] >> bit) & 1u;
        rd = rank | (dup << 31);
    }
    rd = __shfl_sync(FULL, rd, lane & ~3);
    unsigned rank = rd & 0x7fffffffu;
    bool dup = (rd >> 31) != 0;

    // two independent float4 transfers per thread
    float4 v0 = __ldcs(&feats[(size_t)i * 8 + s]);
    float4 v1 = __ldcs(&feats[(size_t)i * 8 + s + 4]);

    // tail rows [U, N) -> zero (disjoint from scatter targets, all < U)
    if ((unsigned)i >= U) {
        float4 z = make_float4(0.f, 0.f, 0.f, 0.f);
        float4* trow = reinterpret_cast<float4*>(out) + (size_t)i * 8;
        __stcs(&trow[s], z);
        __stcs(&trow[s + 4], z);
    }

    float* dst = out + (size_t)rank * NCH + s * 4;
    if (!dup) {
        __stcs(reinterpret_cast<float4*>(dst), v0);
        __stcs(reinterpret_cast<float4*>(dst + 16), v1);
    } else {
        atomicAdd(dst + 0,  v0.x);
        atomicAdd(dst + 1,  v0.y);
        atomicAdd(dst + 2,  v0.z);
        atomicAdd(dst + 3,  v0.w);
        atomicAdd(dst + 16, v1.x);
        atomicAdd(dst + 17, v1.y);
        atomicAdd(dst + 18, v1.z);
        atomicAdd(dst + 19, v1.w);
    }
}

// ------------------------------------------------------------------
extern "C" void kernel_launch(void* const* d_in, const int* in_sizes, int n_in,
                              void* d_out, int out_size) {
    const int4*   coords = (const int4*)d_in[0];     // [N,4] int32
    const float4* feats  = (const float4*)d_in[1];   // [N,32] f32 as [N,8] float4
    float*        out    = (float*)d_out;            // [N,32] f32

    (void)in_sizes; (void)n_in; (void)out_size;

    const int TB = 256;

    // K1: reset bitmaps + lookback descriptors
    k_zero_bits<<<NWORDS / 4 / TB, TB>>>();
    // K2: keys + presence + dup detection (2 points/thread)
    k_mark<<<(NPTS / 2 + TB - 1) / TB, TB>>>(coords);
    // K3: fused single-pass scan + prefix + dup-row zero + U
    k_scan_fused<<<SCAN_NBLK, SCAN_TPB>>>((float4*)d_out);
    // K4: scatter + tail zero (4 threads/row)
    k_scatter<<<(NPTS * 4) / TB, TB>>>(feats, out);
}